// round 12
// baseline (speedup 1.0000x reference)
#include <cuda_runtime.h>

#define EPSF 1e-7f
#define ACLIPF (1.0f - 1e-6f)
#define PI_F 3.14159274101257324f
#define PI_HALF_F 1.57079637050628662f

// Scratch for deterministic single-launch reduction (no device allocs allowed).
static __device__ float g_partials[8192];
static __device__ unsigned int g_ticket = 0;   // self-resetting via atomicInc wrap

__device__ __forceinline__ float fsqrt_approx(float x) {   // single MUFU.SQRT
    float r; asm("sqrt.approx.f32 %0, %1;" : "=f"(r) : "f"(x)); return r;
}
__device__ __forceinline__ float frcp_approx(float x) {    // single MUFU.RCP
    float r; asm("rcp.approx.f32 %0, %1;" : "=f"(r) : "f"(x)); return r;
}

// acos approximation for x in [0,1): abs err <= ~6.8e-5
__device__ __forceinline__ float facos_pos(float x) {
    float p = fmaf(x, -0.0187293f, 0.0742610f);
    p = fmaf(x, p, -0.2121144f);
    p = fmaf(x, p, 1.5707288f);
    return fsqrt_approx(1.0f - x) * p;   // 1-x >= 1e-6 after clipping
}

// acos for x in (-1,1), branchless: acos(x) = off + s*acos_pos(|x|)
__device__ __forceinline__ float facos(float x) {
    float v = facos_pos(fabsf(x));
    float s = copysignf(1.0f, x);
    float off = fmaf(s, -PI_HALF_F, PI_HALF_F);
    return fmaf(s, v, off);
}

// Branchless circle-GIoU with radius sorting (R >= r):
//  - e = R^2 - r^2 >= 0, rdiff = R - r >= 0 (no abs needed)
//  - cosR = (d2+e)/(2dR) >= 0  -> sign-free acos
//  - one MUFU.RCP serves both 1/R and 1/r
// Clipped-acos saturation covers contained/disjoint regions (no selects).
__device__ __forceinline__ float giou_loss(float cx0, float cy0, float r0,
                                           float cx1, float cy1, float r1) {
    float dx = cx0 - cx1, dy = cy0 - cy1;
    float d2 = fmaf(dx, dx, dy * dy);
    float d2c = fmaxf(d2, EPSF);
    float inv_d = rsqrtf(d2c);
    float half_invd = 0.5f * inv_d;

    float R = fmaxf(r0, r1), r = fminf(r0, r1);
    float Rs = R * R, rs = r * r;
    float e = Rs - rs;                   // >= 0
    float rsum  = R + r;
    float rdiff = R - r;                 // >= 0
    float rsum2  = rsum * rsum;
    float rdiff2 = rdiff * rdiff;

    // shared reciprocal: 1/R = r*q, 1/r = R*q with q = rcp(R*r)
    float q = frcp_approx(fmaxf(R * r, 1e-12f));

    // cosR = (d2+e)*half_invd/R >= 0: upper clip only, sign-free acos
    float cosR = (d2 + e) * half_invd * (r * q);
    cosR = fminf(fmaxf(cosR, 0.0f), ACLIPF);
    float acosR = facos_pos(cosR);
    // cosr = (d2-e)*half_invd/r: full range
    float cosr = (d2 - e) * half_invd * (R * q);
    cosr = fminf(fmaxf(cosr, -ACLIPF), ACLIPF);
    float acosr = facos(cosr);

    // h2 = d2 - rdiff^2 shared by t and hull
    float h2 = d2c - rdiff2;
    float sqrt_t = fsqrt_approx(fmaxf((rsum2 - d2c) * h2, EPSF));
    // unconditional inter: saturates to pi*r^2 (contained) / 0 (disjoint)
    float inter = fmaf(Rs, acosR, fmaf(rs, acosr, -0.5f * sqrt_t));

    float uni = fmaf(PI_F, Rs + rs, -inter);

    // unconditional hull: alpha saturates so hull -> pi*R^2 when contained
    float alpha = facos_pos(fminf(rdiff * inv_d, ACLIPF));
    float sqrt_h2 = fsqrt_approx(fmaxf(h2, EPSF));
    float hull = fmaf(rsum, sqrt_h2, fmaf(alpha, -e, PI_F * Rs));

    // loss = 2 - (inter/U + uni/H) = 2 - (inter*H + uni*U)/(U*H)
    float U = fmaxf(uni, EPSF), H = fmaxf(hull, EPSF);
    float num = fmaf(inter, H, uni * U);
    return 2.0f - __fdividef(num, U * H);
}

// Flat one-shot launch (elastic block scheduling beats persistent loops here):
// 4 elements per thread via 3 float4 loads per input (coalesced 128-bit).
// __launch_bounds__(256, 8): cap at 32 regs -> 2048 threads/SM resident.
// Last block (ticket pattern) folds g_partials -> out[0] in a fixed order.
__global__ void __launch_bounds__(256, 8) giou_fused_kernel(
    const float* __restrict__ x, const float* __restrict__ y,
    float* __restrict__ out, int n) {
    int quad = blockIdx.x * blockDim.x + threadIdx.x;
    int base = quad * 4;
    float acc = 0.0f;

    if (base + 3 < n) {
        const float4* x4 = (const float4*)x;
        const float4* y4 = (const float4*)y;
        float4 xa = x4[quad * 3 + 0];
        float4 ya = y4[quad * 3 + 0];
        float4 xb = x4[quad * 3 + 1];
        float4 yb = y4[quad * 3 + 1];
        float4 xc = x4[quad * 3 + 2];
        float4 yc = y4[quad * 3 + 2];
        acc += giou_loss(xa.x, xa.y, xa.z, ya.x, ya.y, ya.z);
        acc += giou_loss(xa.w, xb.x, xb.y, ya.w, yb.x, yb.y);
        acc += giou_loss(xb.z, xb.w, xc.x, yb.z, yb.w, yc.x);
        acc += giou_loss(xc.y, xc.z, xc.w, yc.y, yc.z, yc.w);
    } else if (base < n) {
        for (int i = base; i < n; i++) {
            acc += giou_loss(x[3*i], x[3*i+1], x[3*i+2],
                             y[3*i], y[3*i+1], y[3*i+2]);
        }
    }

    // block reduce
    #pragma unroll
    for (int off = 16; off > 0; off >>= 1)
        acc += __shfl_xor_sync(0xFFFFFFFFu, acc, off);

    __shared__ float warp_sums[8];
    __shared__ bool amLast;
    int lane = threadIdx.x & 31;
    int wid  = threadIdx.x >> 5;
    if (lane == 0) warp_sums[wid] = acc;
    __syncthreads();
    if (wid == 0) {
        float v = (lane < 8) ? warp_sums[lane] : 0.0f;
        #pragma unroll
        for (int off = 4; off > 0; off >>= 1)
            v += __shfl_xor_sync(0xFFFFFFFFu, v, off);
        if (lane == 0) {
            g_partials[blockIdx.x] = v;
            __threadfence();
            unsigned int t = atomicInc(&g_ticket, gridDim.x - 1); // wraps to 0 on last
            amLast = (t == gridDim.x - 1);
        }
    }
    __syncthreads();

    if (amLast) {
        __threadfence();
        int nblocks = gridDim.x;
        float a2 = 0.0f;
        for (int i = threadIdx.x; i < nblocks; i += 256)
            a2 += g_partials[i];                      // fixed order -> deterministic
        #pragma unroll
        for (int off = 16; off > 0; off >>= 1)
            a2 += __shfl_xor_sync(0xFFFFFFFFu, a2, off);
        __syncthreads();                              // reuse warp_sums safely
        if (lane == 0) warp_sums[wid] = a2;
        __syncthreads();
        if (wid == 0) {
            float v = (lane < 8) ? warp_sums[lane] : 0.0f;
            #pragma unroll
            for (int off = 4; off > 0; off >>= 1)
                v += __shfl_xor_sync(0xFFFFFFFFu, v, off);
            if (lane == 0) out[0] = v;
        }
    }
}

extern "C" void kernel_launch(void* const* d_in, const int* in_sizes, int n_in,
                              void* d_out, int out_size) {
    const float* x = (const float*)d_in[0];
    const float* y = (const float*)d_in[1];
    int n = in_sizes[0] / 3;                 // number of circle pairs
    int quads = (n + 3) / 4;                 // 4 elements per thread
    int threads = 256;
    int blocks = (quads + threads - 1) / threads;  // 4096 for N=4194304
    if (blocks > 8192) blocks = 8192;        // g_partials capacity (N fits anyway)

    giou_fused_kernel<<<blocks, threads>>>(x, y, (float*)d_out, n);
}